// round 16
// baseline (speedup 1.0000x reference)
#include <cuda_runtime.h>
#include <cuda_fp16.h>
#include <math.h>
#include <stdint.h>

// Problem constants
#define BB 128
#define NN 1024
#define UU 128
#define NM 3
#define SBLK 132           // per-step block: 128 hvec + 1 inp + 3 pad
#define KPAD 416           // 3*132 = 396 -> 416 (13 x 32)
#define NKC 13             // K chunks of 32
#define MROWS 131072
#define MAX_NNZ 64
#define NSTAGE 3           // GEMM pipeline depth (BK=32)
#define GSM_BYTES (NSTAGE * 2 * 128 * 40 * 2)   // 61440

// g_Xh row layout (stride KPAD, fp16):
//   [0..127] x0 hvec  [128] x0 inp [129..131] pad
//   [132..259] x1     [260] x1 inp [261..263] pad
//   [264..391] x2     [392] x2 inp [393..415] pad

// ---------------- scratch -----------------------------------------------------
__device__ __half g_h16[(size_t)MROWS * UU];    // fp16 copy of h input
__device__ __half g_Xh[(size_t)MROWS * KPAD];   // fp16 Xcat (A operand)
__device__ __half g_rh[(size_t)MROWS * UU];     // r*h (fp16)
__device__ float  g_u [(size_t)MROWS * UU];
__device__ float  g_X1i[(size_t)MROWS];         // fp32 x1 of inp channel
__device__ __half g_Wgt[256 * KPAD];            // gate W^T [N][K] fp16
__device__ __half g_Wct[128 * KPAD];            // cand W^T [N][K] fp16
__device__ int    g_csr_cnt[NN];
__device__ int    g_csr_col[NN * MAX_NNZ];
__device__ float  g_csr_val[NN * MAX_NNZ];

// ---------------- helpers -----------------------------------------------------
__device__ __forceinline__ unsigned smem_u32(const void* p) {
    return (unsigned)__cvta_generic_to_shared(p);
}
__device__ __forceinline__ void cp16(unsigned dst, const void* src) {
    asm volatile("cp.async.cg.shared.global [%0], [%1], 16;" :: "r"(dst), "l"(src));
}
__device__ __forceinline__ void cp_commit() { asm volatile("cp.async.commit_group;"); }
__device__ __forceinline__ void cp_wait1()  { asm volatile("cp.async.wait_group 1;"); }

__device__ __forceinline__ void ldsm_x4(uint32_t* r, uint32_t a) {
    asm volatile("ldmatrix.sync.aligned.m8n8.x4.shared.b16 {%0,%1,%2,%3}, [%4];"
                 : "=r"(r[0]), "=r"(r[1]), "=r"(r[2]), "=r"(r[3]) : "r"(a));
}
__device__ __forceinline__ void mma_f16(float* c, const uint32_t* a, const uint32_t* b) {
    asm volatile("mma.sync.aligned.m16n8k16.row.col.f32.f16.f16.f32 "
                 "{%0,%1,%2,%3}, {%4,%5,%6,%7}, {%8,%9}, {%0,%1,%2,%3};"
                 : "+f"(c[0]), "+f"(c[1]), "+f"(c[2]), "+f"(c[3])
                 : "r"(a[0]), "r"(a[1]), "r"(a[2]), "r"(a[3]), "r"(b[0]), "r"(b[1]));
}

__device__ __forceinline__ void h_store4(__half* p, float4 v) {
    __half2 h01 = __floats2half2_rn(v.x, v.y);
    __half2 h23 = __floats2half2_rn(v.z, v.w);
    uint2 u; u.x = *(uint32_t*)&h01; u.y = *(uint32_t*)&h23;
    *(uint2*)p = u;
}
__device__ __forceinline__ void h_store1pad(__half* p, float v) {
    __half2 h = __floats2half2_rn(v, 0.f);
    uint2 u; u.x = *(uint32_t*)&h; u.y = 0u;
    *(uint2*)p = u;
}
__device__ __forceinline__ float4 h_load4(const __half* p) {
    uint2 u = *(const uint2*)p;
    __half2 p01 = *(__half2*)&u.x, p23 = *(__half2*)&u.y;
    float2 f01 = __half22float2(p01), f23 = __half22float2(p23);
    return make_float4(f01.x, f01.y, f23.x, f23.y);
}
__device__ __forceinline__ void fma4(float4& a, float s, float4 v) {
    a.x = fmaf(s, v.x, a.x); a.y = fmaf(s, v.y, a.y);
    a.z = fmaf(s, v.z, a.z); a.w = fmaf(s, v.w, a.w);
}

// 4-way unrolled fp16 sparse gather, 4 independent accumulators, uniform lanes
__device__ __forceinline__ void gather_acc_h(
    const __half* __restrict__ base, size_t rowstride, int lane,
    const int* scol, const float* sval, int cnt, float4& aout)
{
    float4 a0 = make_float4(0.f,0.f,0.f,0.f), a1v = a0, a2 = a0, a3 = a0;
    int i = 0;
    for (; i + 4 <= cnt; i += 4) {
        int n0 = scol[i], n1 = scol[i+1], n2 = scol[i+2], n3 = scol[i+3];
        float s0 = sval[i], s1 = sval[i+1], s2 = sval[i+2], s3 = sval[i+3];
        float4 v0 = h_load4(base + (size_t)n0 * rowstride + lane * 4);
        float4 v1 = h_load4(base + (size_t)n1 * rowstride + lane * 4);
        float4 v2 = h_load4(base + (size_t)n2 * rowstride + lane * 4);
        float4 v3 = h_load4(base + (size_t)n3 * rowstride + lane * 4);
        fma4(a0, s0, v0);
        fma4(a1v, s1, v1);
        fma4(a2, s2, v2);
        fma4(a3, s3, v3);
    }
    for (; i < cnt; i++) {
        float s = sval[i];
        float4 v = h_load4(base + (size_t)scol[i] * rowstride + lane * 4);
        fma4(a0, s, v);
    }
    a0.x += a1v.x; a0.y += a1v.y; a0.z += a1v.z; a0.w += a1v.w;
    a2.x += a3.x;  a2.y += a3.y;  a2.z += a3.z;  a2.w += a3.w;
    aout.x = a0.x + a2.x; aout.y = a0.y + a2.y;
    aout.z = a0.z + a2.z; aout.w = a0.w + a2.w;
}

// ---------------- merged setup: h2half | csr_build | wtrans x2 ----------------
#define SETUP_H2H   16384
#define SETUP_CSR   (SETUP_H2H + 128)
#define SETUP_WG    (SETUP_CSR + KPAD)
#define SETUP_TOTAL (SETUP_WG + KPAD)

__global__ void __launch_bounds__(256) setup_all(
    const float* __restrict__ h, const float* __restrict__ S,
    const float* __restrict__ gw, const float* __restrict__ cw)
{
    int bx = blockIdx.x, tid = threadIdx.x;
    if (bx < SETUP_H2H) {
        size_t i = (size_t)bx * 256 + tid;
        float4 v = *(const float4*)(h + i * 4);
        h_store4(g_h16 + i * 4, v);
    } else if (bx < SETUP_CSR) {
        int w = ((bx - SETUP_H2H) * 256 + tid) >> 5;
        int lane = tid & 31;
        if (w >= NN) return;
        const float* row = S + (size_t)w * NN;
        int cnt = 0;
        for (int base = 0; base < NN; base += 32) {
            float v = row[base + lane];
            unsigned m = __ballot_sync(0xffffffffu, v != 0.f);
            if (v != 0.f) {
                int pos = cnt + __popc(m & ((1u << lane) - 1u));
                if (pos < MAX_NNZ) {
                    g_csr_col[w * MAX_NNZ + pos] = base + lane;
                    g_csr_val[w * MAX_NNZ + pos] = v;
                }
            }
            cnt += __popc(m);
        }
        if (lane == 0) g_csr_cnt[w] = cnt < MAX_NNZ ? cnt : MAX_NNZ;
    } else if (bx < SETUP_WG) {
        int k = bx - SETUP_CSR, j = tid;           // gate: 256 cols
        int s = k / SBLK, c = k - s * SBLK;
        float v = 0.f;
        if (s < NM && c < 129) {
            int corig = (c == 128) ? 0 : (c + 1);
            v = gw[(size_t)(corig * NM + s) * 256 + j];
        }
        g_Wgt[(size_t)j * KPAD + k] = __float2half_rn(v);
    } else {
        int k = bx - SETUP_WG, j = tid;            // cand: 128 cols
        if (j >= 128) return;
        int s = k / SBLK, c = k - s * SBLK;
        float v = 0.f;
        if (s < NM && c < 129) {
            int corig = (c == 128) ? 0 : (c + 1);
            v = cw[(size_t)(corig * NM + s) * 128 + j];
        }
        g_Wct[(size_t)j * KPAD + k] = __float2half_rn(v);
    }
}

// ---------------- diffusion pass 1: x0 copy + x1 (=S@x0) ----------------------
// Main blocks (bx < NN): hvec channels, uniform lanes.
// Extra blocks (bx >= NN, 8 per y-slice): inp-channel diffusion (scalar).
template <int USE_RH>
__global__ void __launch_bounds__(128) spmm_pass1(const float* __restrict__ inp) {
    const __half* __restrict__ hvec = USE_RH ? (const __half*)g_rh : (const __half*)g_h16;
    if (blockIdx.x >= NN) {
        int m = (blockIdx.x - NN) * 128 + threadIdx.x;   // 0..1023
        int cnt = g_csr_cnt[m];
#pragma unroll
        for (int bq = 0; bq < 4; bq++) {
            int b = blockIdx.y * 4 + bq;
            const float* ib = inp + (size_t)b * NN;
            float a1 = 0.f;
            for (int i = 0; i < cnt; i++)
                a1 = fmaf(g_csr_val[m * MAX_NNZ + i], ib[g_csr_col[m * MAX_NNZ + i]], a1);
            size_t rowm = (size_t)b * NN + m;
            __half* Xh = g_Xh + rowm * KPAD;
            h_store1pad(Xh + 128, ib[m]);   // x0 inp + pads 129..131
            h_store1pad(Xh + 260, a1);      // x1 inp + pads 261..263
            g_X1i[rowm] = a1;
        }
        return;
    }
    int m = blockIdx.x;
    int g = threadIdx.x >> 5, lane = threadIdx.x & 31;
    int b = blockIdx.y * 4 + g;
    __shared__ int   scol[MAX_NNZ];
    __shared__ float sval[MAX_NNZ];
    int cnt = g_csr_cnt[m];
    if (threadIdx.x < MAX_NNZ) {
        scol[threadIdx.x] = g_csr_col[m * MAX_NNZ + threadIdx.x];
        sval[threadIdx.x] = g_csr_val[m * MAX_NNZ + threadIdx.x];
    }
    __syncthreads();

    size_t rowm = (size_t)b * NN + m;
    float4 a;
    gather_acc_h(hvec + (size_t)b * NN * UU, UU, lane, scol, sval, cnt, a);

    __half* Xh = g_Xh + rowm * KPAD;
    *(uint2*)(Xh + lane * 4) = *(const uint2*)(hvec + rowm * UU + lane * 4);
    h_store4(Xh + 132 + lane * 4, a);
}

// ---------------- diffusion pass 2: x2 = 2*S@x1 - x0 --------------------------
template <int USE_RH>
__global__ void __launch_bounds__(128) spmm_pass2(const float* __restrict__ inp) {
    const __half* __restrict__ hvec = USE_RH ? (const __half*)g_rh : (const __half*)g_h16;
    if (blockIdx.x >= NN) {
        int m = (blockIdx.x - NN) * 128 + threadIdx.x;
        int cnt = g_csr_cnt[m];
#pragma unroll
        for (int bq = 0; bq < 4; bq++) {
            int b = blockIdx.y * 4 + bq;
            size_t rowb = (size_t)b * NN;
            float a1 = 0.f;
            for (int i = 0; i < cnt; i++)
                a1 = fmaf(g_csr_val[m * MAX_NNZ + i], g_X1i[rowb + g_csr_col[m * MAX_NNZ + i]], a1);
            size_t rowm = rowb + m;
            h_store1pad(g_Xh + rowm * KPAD + 392, 2.f * a1 - inp[rowm]);  // 392..395
        }
        return;
    }
    int m = blockIdx.x;
    int g = threadIdx.x >> 5, lane = threadIdx.x & 31;
    int b = blockIdx.y * 4 + g;
    __shared__ int   scol[MAX_NNZ];
    __shared__ float sval[MAX_NNZ];
    int cnt = g_csr_cnt[m];
    if (threadIdx.x < MAX_NNZ) {
        scol[threadIdx.x] = g_csr_col[m * MAX_NNZ + threadIdx.x];
        sval[threadIdx.x] = g_csr_val[m * MAX_NNZ + threadIdx.x];
    }
    __syncthreads();

    size_t rowm = (size_t)b * NN + m;
    float4 a;
    gather_acc_h(g_Xh + (size_t)b * NN * KPAD + 132, KPAD, lane, scol, sval, cnt, a);

    float4 x0 = h_load4(hvec + rowm * UU + lane * 4);
    float4 r;
    r.x = 2.f * a.x - x0.x;
    r.y = 2.f * a.y - x0.y;
    r.z = 2.f * a.z - x0.z;
    r.w = 2.f * a.w - x0.w;

    __half* Xh = g_Xh + rowm * KPAD;
    h_store4(Xh + 264 + lane * 4, r);                            // cols 264..391
    if (lane < 5) {                                              // pads 396..415
        uint2 z; z.x = 0u; z.y = 0u;
        *(uint2*)(Xh + 396 + lane * 4) = z;
    }
}

// ---------------- fp16 tensor-core GEMM, BK=32, 3-stage dynamic-smem pipeline -
// BM=128 BN=128, 256 thr (8 warps 4Mx2N), warp tile 32x64, m16n8k16.
// Stage = A[128x40] + B[128x40] halves (pitch 40, conflict-free ldsm).
// MODE 0: gate (Wgt, N=256, grid.y=2): by0 -> g_rh(fp16) = sig*h ; by1 -> g_u = sig
// MODE 1: cand (Wct, N=128): newh = u*h+(1-u)*tanh ; fused proj -> out
template <int MODE>
__global__ void __launch_bounds__(256) gemm_kernel(
    const float* __restrict__ bias, const float* __restrict__ hvec,
    float* __restrict__ newh, const float* __restrict__ pw,
    const float* __restrict__ pb, float* __restrict__ out)
{
    extern __shared__ __align__(16) char dsm[];
    typedef __half (*SMv)[2][128 * 40];
    SMv SM = (SMv)dsm;
    float* srow = (float*)dsm;                 // aliased; post-mainloop only

    const int tid = threadIdx.x;
    const int lane = tid & 31, wid = tid >> 5;
    const int wm = wid >> 1, wn = wid & 1;
    const size_t mbase = (size_t)blockIdx.x * 128;
    const int jb = (MODE == 0) ? blockIdx.y * 128 : 0;

    const __half* __restrict__ Wt = (MODE == 0) ? g_Wgt : g_Wct;

    // load mapping: f in [0,512) per matrix: lrow=f>>2, lq=f&3 (8 halves each)
    const int r0 = tid >> 2,        q0 = (tid & 3) * 8;
    const int r1 = (tid + 256) >> 2, q1 = ((tid + 256) & 3) * 8;
    const __half* srcA0 = g_Xh + (mbase + r0) * KPAD + q0;
    const __half* srcA1 = g_Xh + (mbase + r1) * KPAD + q1;
    const __half* srcB0 = Wt + (size_t)(jb + r0) * KPAD + q0;
    const __half* srcB1 = Wt + (size_t)(jb + r1) * KPAD + q1;
    const int d0 = r0 * 40 + q0, d1 = r1 * 40 + q1;

    float c[2][8][4];
#pragma unroll
    for (int mt = 0; mt < 2; mt++)
#pragma unroll
        for (int j = 0; j < 8; j++)
#pragma unroll
            for (int q = 0; q < 4; q++) c[mt][j][q] = 0.f;

    // preload stages 0..1
#pragma unroll
    for (int s = 0; s < NSTAGE - 1; s++) {
        int k0 = s * 32;
        cp16(smem_u32(&SM[s][0][d0]), srcA0 + k0);
        cp16(smem_u32(&SM[s][0][d1]), srcA1 + k0);
        cp16(smem_u32(&SM[s][1][d0]), srcB0 + k0);
        cp16(smem_u32(&SM[s][1][d1]), srcB1 + k0);
        cp_commit();
    }

    // fragment addressing
    const int la = lane & 15;
    const int ka = (lane & 16) ? 8 : 0;
    const int arow = wm * 32 + la;
    const int nb = lane & 7;
    const int kb = (lane & 8) ? 8 : 0;
    const int joff = (lane & 16) ? 8 : 0;

    int cur = 0;
    for (int t = 0; t < NKC; t++) {
        cp_wait1();
        __syncthreads();
        {
            int tp = t + NSTAGE - 1;
            int nst = cur + (NSTAGE - 1); if (nst >= NSTAGE) nst -= NSTAGE;
            if (tp < NKC) {
                int k0 = tp * 32;
                cp16(smem_u32(&SM[nst][0][d0]), srcA0 + k0);
                cp16(smem_u32(&SM[nst][0][d1]), srcA1 + k0);
                cp16(smem_u32(&SM[nst][1][d0]), srcB0 + k0);
                cp16(smem_u32(&SM[nst][1][d1]), srcB1 + k0);
            }
            cp_commit();
        }

#pragma unroll
        for (int ks = 0; ks < 2; ks++) {
            uint32_t ah[2][4];
#pragma unroll
            for (int mt = 0; mt < 2; mt++)
                ldsm_x4(ah[mt], smem_u32(&SM[cur][0][(arow + mt * 16) * 40 + ks * 16 + ka]));
#pragma unroll
            for (int jj = 0; jj < 8; jj += 2) {
                uint32_t bb[4];
                int bi = (wn * 64 + jj * 8 + joff + nb) * 40 + ks * 16 + kb;
                ldsm_x4(bb, smem_u32(&SM[cur][1][bi]));
#pragma unroll
                for (int mt = 0; mt < 2; mt++) {
                    mma_f16(c[mt][jj],     ah[mt], bb);
                    mma_f16(c[mt][jj + 1], ah[mt], bb + 2);
                }
            }
        }
        if (++cur == NSTAGE) cur = 0;
    }

    // epilogue
    float part[2][2];
    if (MODE == 1) { part[0][0] = part[0][1] = part[1][0] = part[1][1] = 0.f; }

#pragma unroll
    for (int mt = 0; mt < 2; mt++) {
#pragma unroll
        for (int j = 0; j < 8; j++) {
            int row0 = (int)mbase + wm * 32 + mt * 16 + (lane >> 2);
            int col = wn * 64 + j * 8 + (lane & 3) * 2;
            int jg = jb + col;
            float b0 = bias[jg], b1 = bias[jg + 1];
#pragma unroll
            for (int h2 = 0; h2 < 2; h2++) {
                int row = row0 + h2 * 8;
                float v0 = c[mt][j][h2 * 2 + 0] + b0;
                float v1 = c[mt][j][h2 * 2 + 1] + b1;
                size_t idx = (size_t)row * UU + col;
                if (MODE == 0) {
                    float s0 = 1.f / (1.f + expf(-v0));
                    float s1 = 1.f / (1.f + expf(-v1));
                    if (jb == 0) {
                        float2 hh = *(const float2*)(hvec + idx);
                        __half2 o = __floats2half2_rn(s0 * hh.x, s1 * hh.y);
                        *(__half2*)(g_rh + idx) = o;
                    } else {
                        float2 o; o.x = s0; o.y = s1;
                        *(float2*)(g_u + idx) = o;
                    }
                } else {
                    float t0 = tanhf(v0), t1 = tanhf(v1);
                    float2 uu = *(const float2*)(g_u + idx);
                    float2 hh = *(const float2*)(hvec + idx);
                    float2 o;
                    o.x = uu.x * hh.x + (1.f - uu.x) * t0;
                    o.y = uu.y * hh.y + (1.f - uu.y) * t1;
                    *(float2*)(newh + idx) = o;
                    part[mt][h2] = fmaf(o.x, pw[col], part[mt][h2]);
                    part[mt][h2] = fmaf(o.y, pw[col + 1], part[mt][h2]);
                }
            }
        }
    }

    if (MODE == 1) {
        __syncthreads();               // SM reads done; safe to alias srow
        if (tid < 128) srow[tid] = 0.f;
        __syncthreads();
#pragma unroll
        for (int mt = 0; mt < 2; mt++)
#pragma unroll
            for (int h2 = 0; h2 < 2; h2++) {
                int lr = wm * 32 + mt * 16 + h2 * 8 + (lane >> 2);
                atomicAdd(&srow[lr], part[mt][h2]);
            }
        __syncthreads();
        if (tid < 128) out[mbase + tid] = srow[tid] + pb[0];
    }
}

// ---------------- launch ------------------------------------------------------
extern "C" void kernel_launch(void* const* d_in, const int* in_sizes, int n_in,
                              void* d_out, int out_size) {
    const float* inp = (const float*)d_in[0];
    const float* h   = (const float*)d_in[1];
    const float* S   = (const float*)d_in[2];
    const float* gw  = (const float*)d_in[3];
    const float* gb  = (const float*)d_in[4];
    const float* cw  = (const float*)d_in[5];
    const float* cb  = (const float*)d_in[6];
    const float* pw  = (const float*)d_in[7];
    const float* pb  = (const float*)d_in[8];
    float* out  = (float*)d_out;
    float* newh = out + MROWS;

    // one-time-safe attribute set (idempotent; not an allocation / stream op)
    cudaFuncSetAttribute(gemm_kernel<0>, cudaFuncAttributeMaxDynamicSharedMemorySize, GSM_BYTES);
    cudaFuncSetAttribute(gemm_kernel<1>, cudaFuncAttributeMaxDynamicSharedMemorySize, GSM_BYTES);

    setup_all<<<SETUP_TOTAL, 256>>>(h, S, gw, cw);

    // gate path
    spmm_pass1<0><<<dim3(NN + 8, BB / 4), 128>>>(inp);
    spmm_pass2<0><<<dim3(NN + 8, BB / 4), 128>>>(inp);
    gemm_kernel<0><<<dim3(MROWS / 128, 2), 256, GSM_BYTES>>>(gb, h, nullptr, nullptr, nullptr, nullptr);

    // cand path (projection fused)
    spmm_pass1<1><<<dim3(NN + 8, BB / 4), 128>>>(inp);
    spmm_pass2<1><<<dim3(NN + 8, BB / 4), 128>>>(inp);
    gemm_kernel<1><<<dim3(MROWS / 128, 1), 256, GSM_BYTES>>>(cb, h, newh, pw, pb, out);
}

// round 17
// speedup vs baseline: 1.1398x; 1.1398x over previous
#include <cuda_runtime.h>
#include <cuda_fp16.h>
#include <math.h>
#include <stdint.h>

// Problem constants
#define BB 128
#define NN 1024
#define UU 128
#define NM 3
#define SBLK 132           // per-step block: 128 hvec + 1 inp + 3 pad
#define KPAD 416           // 3*132 = 396 -> 416 (13 x 32)
#define NKC 13             // GEMM K chunks of 32
#define MROWS 131072
#define MAX_NNZ 64
#define NSTAGE 3           // GEMM pipeline depth (BK=32)
#define GSM_BYTES (NSTAGE * 2 * 128 * 40 * 2)   // 61440

// g_Xh row layout (stride KPAD, fp16):
//   [0..127] x0 hvec  [128] x0 inp [129..131] pad
//   [132..259] x1     [260] x1 inp [261..263] pad
//   [264..391] x2     [392] x2 inp [393..415] pad

// ---------------- scratch -----------------------------------------------------
__device__ __half g_h16[(size_t)MROWS * UU];    // fp16 copy of h input
__device__ __half g_Xh[(size_t)MROWS * KPAD];   // fp16 Xcat (A operand)
__device__ __half g_rh[(size_t)MROWS * UU];     // r*h (fp16)
__device__ float  g_u [(size_t)MROWS * UU];
__device__ __half g_Wgt[256 * KPAD];            // gate W^T [N][K] fp16
__device__ __half g_Wct[128 * KPAD];            // cand W^T [N][K] fp16
__device__ int    g_csr_cnt[NN];
__device__ int    g_csr_col[NN * MAX_NNZ];
__device__ float  g_csr_val[NN * MAX_NNZ];

// ---------------- helpers -----------------------------------------------------
__device__ __forceinline__ unsigned smem_u32(const void* p) {
    return (unsigned)__cvta_generic_to_shared(p);
}
__device__ __forceinline__ void cp16(unsigned dst, const void* src) {
    asm volatile("cp.async.cg.shared.global [%0], [%1], 16;" :: "r"(dst), "l"(src));
}
__device__ __forceinline__ void cp_commit() { asm volatile("cp.async.commit_group;"); }
__device__ __forceinline__ void cp_wait1()  { asm volatile("cp.async.wait_group 1;"); }

__device__ __forceinline__ void ldsm_x4(uint32_t* r, uint32_t a) {
    asm volatile("ldmatrix.sync.aligned.m8n8.x4.shared.b16 {%0,%1,%2,%3}, [%4];"
                 : "=r"(r[0]), "=r"(r[1]), "=r"(r[2]), "=r"(r[3]) : "r"(a));
}
__device__ __forceinline__ void mma_f16(float* c, const uint32_t* a, const uint32_t* b) {
    asm volatile("mma.sync.aligned.m16n8k16.row.col.f32.f16.f16.f32 "
                 "{%0,%1,%2,%3}, {%4,%5,%6,%7}, {%8,%9}, {%0,%1,%2,%3};"
                 : "+f"(c[0]), "+f"(c[1]), "+f"(c[2]), "+f"(c[3])
                 : "r"(a[0]), "r"(a[1]), "r"(a[2]), "r"(a[3]), "r"(b[0]), "r"(b[1]));
}

__device__ __forceinline__ void h_store4(__half* p, float4 v) {
    __half2 h01 = __floats2half2_rn(v.x, v.y);
    __half2 h23 = __floats2half2_rn(v.z, v.w);
    uint2 u; u.x = *(uint32_t*)&h01; u.y = *(uint32_t*)&h23;
    *(uint2*)p = u;
}
__device__ __forceinline__ void h_store1pad(__half* p, float v) {
    __half2 h = __floats2half2_rn(v, 0.f);
    uint2 u; u.x = *(uint32_t*)&h; u.y = 0u;
    *(uint2*)p = u;
}
__device__ __forceinline__ float4 h_load4(const __half* p) {
    uint2 u = *(const uint2*)p;
    __half2 p01 = *(__half2*)&u.x, p23 = *(__half2*)&u.y;
    float2 f01 = __half22float2(p01), f23 = __half22float2(p23);
    return make_float4(f01.x, f01.y, f23.x, f23.y);
}
__device__ __forceinline__ void fma4(float4& a, float s, float4 v) {
    a.x = fmaf(s, v.x, a.x); a.y = fmaf(s, v.y, a.y);
    a.z = fmaf(s, v.z, a.z); a.w = fmaf(s, v.w, a.w);
}

// 4-way unrolled fp16 sparse gather with 4 independent accumulators;
// lane0 also accumulates the inp-channel scalar stream from sextra.
__device__ __forceinline__ void gather_acc_h(
    const __half* __restrict__ base, size_t rowstride, int lane,
    const int* scol, const float* sval, int cnt,
    const float* sextra, float4& aout, float& a1out, bool lane0)
{
    float4 a0 = make_float4(0.f,0.f,0.f,0.f), a1v = a0, a2 = a0, a3 = a0;
    float e0 = 0.f, e1 = 0.f, e2 = 0.f, e3 = 0.f;
    int i = 0;
    for (; i + 4 <= cnt; i += 4) {
        int n0 = scol[i], n1 = scol[i+1], n2 = scol[i+2], n3 = scol[i+3];
        float s0 = sval[i], s1 = sval[i+1], s2 = sval[i+2], s3 = sval[i+3];
        float4 v0 = h_load4(base + (size_t)n0 * rowstride + lane * 4);
        float4 v1 = h_load4(base + (size_t)n1 * rowstride + lane * 4);
        float4 v2 = h_load4(base + (size_t)n2 * rowstride + lane * 4);
        float4 v3 = h_load4(base + (size_t)n3 * rowstride + lane * 4);
        fma4(a0, s0, v0);
        fma4(a1v, s1, v1);
        fma4(a2, s2, v2);
        fma4(a3, s3, v3);
        if (lane0) {
            e0 = fmaf(s0, sextra[i],   e0);
            e1 = fmaf(s1, sextra[i+1], e1);
            e2 = fmaf(s2, sextra[i+2], e2);
            e3 = fmaf(s3, sextra[i+3], e3);
        }
    }
    for (; i < cnt; i++) {
        float s = sval[i];
        float4 v = h_load4(base + (size_t)scol[i] * rowstride + lane * 4);
        fma4(a0, s, v);
        if (lane0) e0 = fmaf(s, sextra[i], e0);
    }
    a0.x += a1v.x; a0.y += a1v.y; a0.z += a1v.z; a0.w += a1v.w;
    a2.x += a3.x;  a2.y += a3.y;  a2.z += a3.z;  a2.w += a3.w;
    aout.x = a0.x + a2.x; aout.y = a0.y + a2.y;
    aout.z = a0.z + a2.z; aout.w = a0.w + a2.w;
    a1out = (e0 + e1) + (e2 + e3);
}

// ---------------- merged setup: h2half | csr_build | wtrans x2 ----------------
#define SETUP_H2H   16384
#define SETUP_CSR   (SETUP_H2H + 128)
#define SETUP_WG    (SETUP_CSR + KPAD)
#define SETUP_TOTAL (SETUP_WG + KPAD)

__global__ void __launch_bounds__(256) setup_all(
    const float* __restrict__ h, const float* __restrict__ S,
    const float* __restrict__ gw, const float* __restrict__ cw)
{
    int bx = blockIdx.x, tid = threadIdx.x;
    if (bx < SETUP_H2H) {
        size_t i = (size_t)bx * 256 + tid;
        float4 v = *(const float4*)(h + i * 4);
        h_store4(g_h16 + i * 4, v);
    } else if (bx < SETUP_CSR) {
        int w = ((bx - SETUP_H2H) * 256 + tid) >> 5;
        int lane = tid & 31;
        if (w >= NN) return;
        const float* row = S + (size_t)w * NN;
        int cnt = 0;
        for (int base = 0; base < NN; base += 32) {
            float v = row[base + lane];
            unsigned m = __ballot_sync(0xffffffffu, v != 0.f);
            if (v != 0.f) {
                int pos = cnt + __popc(m & ((1u << lane) - 1u));
                if (pos < MAX_NNZ) {
                    g_csr_col[w * MAX_NNZ + pos] = base + lane;
                    g_csr_val[w * MAX_NNZ + pos] = v;
                }
            }
            cnt += __popc(m);
        }
        if (lane == 0) g_csr_cnt[w] = cnt < MAX_NNZ ? cnt : MAX_NNZ;
    } else if (bx < SETUP_WG) {
        int k = bx - SETUP_CSR, j = tid;           // gate: 256 cols
        int s = k / SBLK, c = k - s * SBLK;
        float v = 0.f;
        if (s < NM && c < 129) {
            int corig = (c == 128) ? 0 : (c + 1);
            v = gw[(size_t)(corig * NM + s) * 256 + j];
        }
        g_Wgt[(size_t)j * KPAD + k] = __float2half_rn(v);
    } else {
        int k = bx - SETUP_WG, j = tid;            // cand: 128 cols
        if (j >= 128) return;
        int s = k / SBLK, c = k - s * SBLK;
        float v = 0.f;
        if (s < NM && c < 129) {
            int corig = (c == 128) ? 0 : (c + 1);
            v = cw[(size_t)(corig * NM + s) * 128 + j];
        }
        g_Wct[(size_t)j * KPAD + k] = __float2half_rn(v);
    }
}

// ---------------- diffusion pass 1: x0 copy + x1 (=S@x0), all fp16 ------------
template <int USE_RH>
__global__ void __launch_bounds__(128) spmm_pass1(const float* __restrict__ inp) {
    const __half* __restrict__ hvec = USE_RH ? (const __half*)g_rh : (const __half*)g_h16;
    int m = blockIdx.x;
    int g = threadIdx.x >> 5, lane = threadIdx.x & 31;
    int b = blockIdx.y * 4 + g;
    __shared__ int   scol[MAX_NNZ];
    __shared__ float sval[MAX_NNZ];
    __shared__ float sinp[4][MAX_NNZ];
    int cnt = g_csr_cnt[m];
    if (threadIdx.x < MAX_NNZ) {
        scol[threadIdx.x] = g_csr_col[m * MAX_NNZ + threadIdx.x];
        sval[threadIdx.x] = g_csr_val[m * MAX_NNZ + threadIdx.x];
    }
    __syncthreads();
    if (lane < cnt) sinp[g][lane] = inp[(size_t)b * NN + scol[lane]];
    if (cnt > 32 && lane + 32 < cnt) sinp[g][lane + 32] = inp[(size_t)b * NN + scol[lane + 32]];
    __syncwarp();

    size_t rowm = (size_t)b * NN + m;
    float4 a; float a1;
    gather_acc_h(hvec + (size_t)b * NN * UU, UU, lane, scol, sval, cnt,
                 sinp[g], a, a1, lane == 0);

    __half* Xh = g_Xh + rowm * KPAD;
    *(uint2*)(Xh + lane * 4) = *(const uint2*)(hvec + rowm * UU + lane * 4);
    h_store4(Xh + 132 + lane * 4, a);
    if (lane == 0) {
        h_store1pad(Xh + 128, inp[rowm]);   // x0 inp + pads 129..131
        h_store1pad(Xh + 260, a1);          // x1 inp + pads 261..263
    }
}

// ---------------- diffusion pass 2: x2 = 2*S@x1 - x0 (x1 from Xh cols 132+) ---
template <int USE_RH>
__global__ void __launch_bounds__(128) spmm_pass2(const float* __restrict__ inp) {
    const __half* __restrict__ hvec = USE_RH ? (const __half*)g_rh : (const __half*)g_h16;
    int m = blockIdx.x;
    int g = threadIdx.x >> 5, lane = threadIdx.x & 31;
    int b = blockIdx.y * 4 + g;
    __shared__ int   scol[MAX_NNZ];
    __shared__ float sval[MAX_NNZ];
    __shared__ float sx1i[4][MAX_NNZ];
    int cnt = g_csr_cnt[m];
    if (threadIdx.x < MAX_NNZ) {
        scol[threadIdx.x] = g_csr_col[m * MAX_NNZ + threadIdx.x];
        sval[threadIdx.x] = g_csr_val[m * MAX_NNZ + threadIdx.x];
    }
    __syncthreads();
    if (lane < cnt)
        sx1i[g][lane] = __half2float(g_Xh[((size_t)b * NN + scol[lane]) * KPAD + 260]);
    if (cnt > 32 && lane + 32 < cnt)
        sx1i[g][lane + 32] = __half2float(g_Xh[((size_t)b * NN + scol[lane + 32]) * KPAD + 260]);
    __syncwarp();

    size_t rowm = (size_t)b * NN + m;
    float4 a; float a1;
    gather_acc_h(g_Xh + (size_t)b * NN * KPAD + 132, KPAD, lane, scol, sval, cnt,
                 sx1i[g], a, a1, lane == 0);

    float4 x0 = h_load4(hvec + rowm * UU + lane * 4);
    float4 r;
    r.x = 2.f * a.x - x0.x;
    r.y = 2.f * a.y - x0.y;
    r.z = 2.f * a.z - x0.z;
    r.w = 2.f * a.w - x0.w;

    __half* Xh = g_Xh + rowm * KPAD;
    h_store4(Xh + 264 + lane * 4, r);                            // cols 264..391
    if (lane == 0) h_store1pad(Xh + 392, 2.f * a1 - inp[rowm]);  // 392..395
    if (lane < 5) {                                              // pads 396..415
        uint2 z; z.x = 0u; z.y = 0u;
        *(uint2*)(Xh + 396 + lane * 4) = z;
    }
}

// ---------------- fp16 tensor-core GEMM, BK=32, 3-stage dynamic-smem pipeline -
// BM=128 BN=128, 256 thr (8 warps 4Mx2N), warp tile 32x64, m16n8k16.
// Stage = A[128x40] + B[128x40] halves (pitch 40, conflict-free ldsm).
// MODE 0: gate (Wgt, N=256, grid.y=2): by0 -> g_rh(fp16) = sig*h ; by1 -> g_u = sig
// MODE 1: cand (Wct, N=128): newh = u*h+(1-u)*tanh ; fused proj -> out
template <int MODE>
__global__ void __launch_bounds__(256) gemm_kernel(
    const float* __restrict__ bias, const float* __restrict__ hvec,
    float* __restrict__ newh, const float* __restrict__ pw,
    const float* __restrict__ pb, float* __restrict__ out)
{
    extern __shared__ __align__(16) char dsm[];
    typedef __half (*SMv)[2][128 * 40];
    SMv SM = (SMv)dsm;
    float* srow = (float*)dsm;                 // aliased; post-mainloop only

    const int tid = threadIdx.x;
    const int lane = tid & 31, wid = tid >> 5;
    const int wm = wid >> 1, wn = wid & 1;
    const size_t mbase = (size_t)blockIdx.x * 128;
    const int jb = (MODE == 0) ? blockIdx.y * 128 : 0;

    const __half* __restrict__ Wt = (MODE == 0) ? g_Wgt : g_Wct;

    const int r0 = tid >> 2,        q0 = (tid & 3) * 8;
    const int r1 = (tid + 256) >> 2, q1 = ((tid + 256) & 3) * 8;
    const __half* srcA0 = g_Xh + (mbase + r0) * KPAD + q0;
    const __half* srcA1 = g_Xh + (mbase + r1) * KPAD + q1;
    const __half* srcB0 = Wt + (size_t)(jb + r0) * KPAD + q0;
    const __half* srcB1 = Wt + (size_t)(jb + r1) * KPAD + q1;
    const int d0 = r0 * 40 + q0, d1 = r1 * 40 + q1;

    float c[2][8][4];
#pragma unroll
    for (int mt = 0; mt < 2; mt++)
#pragma unroll
        for (int j = 0; j < 8; j++)
#pragma unroll
            for (int q = 0; q < 4; q++) c[mt][j][q] = 0.f;

    // preload stages 0..1
#pragma unroll
    for (int s = 0; s < NSTAGE - 1; s++) {
        int k0 = s * 32;
        cp16(smem_u32(&SM[s][0][d0]), srcA0 + k0);
        cp16(smem_u32(&SM[s][0][d1]), srcA1 + k0);
        cp16(smem_u32(&SM[s][1][d0]), srcB0 + k0);
        cp16(smem_u32(&SM[s][1][d1]), srcB1 + k0);
        cp_commit();
    }

    const int la = lane & 15;
    const int ka = (lane & 16) ? 8 : 0;
    const int arow = wm * 32 + la;
    const int nb = lane & 7;
    const int kb = (lane & 8) ? 8 : 0;
    const int joff = (lane & 16) ? 8 : 0;

    int cur = 0;
    for (int t = 0; t < NKC; t++) {
        cp_wait1();
        __syncthreads();
        {
            int tp = t + NSTAGE - 1;
            int nst = cur + (NSTAGE - 1); if (nst >= NSTAGE) nst -= NSTAGE;
            if (tp < NKC) {
                int k0 = tp * 32;
                cp16(smem_u32(&SM[nst][0][d0]), srcA0 + k0);
                cp16(smem_u32(&SM[nst][0][d1]), srcA1 + k0);
                cp16(smem_u32(&SM[nst][1][d0]), srcB0 + k0);
                cp16(smem_u32(&SM[nst][1][d1]), srcB1 + k0);
            }
            cp_commit();
        }

#pragma unroll
        for (int ks = 0; ks < 2; ks++) {
            uint32_t ah[2][4];
#pragma unroll
            for (int mt = 0; mt < 2; mt++)
                ldsm_x4(ah[mt], smem_u32(&SM[cur][0][(arow + mt * 16) * 40 + ks * 16 + ka]));
#pragma unroll
            for (int jj = 0; jj < 8; jj += 2) {
                uint32_t bb[4];
                int bi = (wn * 64 + jj * 8 + joff + nb) * 40 + ks * 16 + kb;
                ldsm_x4(bb, smem_u32(&SM[cur][1][bi]));
#pragma unroll
                for (int mt = 0; mt < 2; mt++) {
                    mma_f16(c[mt][jj],     ah[mt], bb);
                    mma_f16(c[mt][jj + 1], ah[mt], bb + 2);
                }
            }
        }
        if (++cur == NSTAGE) cur = 0;
    }

    // epilogue
    float part[2][2];
    if (MODE == 1) { part[0][0] = part[0][1] = part[1][0] = part[1][1] = 0.f; }

#pragma unroll
    for (int mt = 0; mt < 2; mt++) {
#pragma unroll
        for (int j = 0; j < 8; j++) {
            int row0 = (int)mbase + wm * 32 + mt * 16 + (lane >> 2);
            int col = wn * 64 + j * 8 + (lane & 3) * 2;
            int jg = jb + col;
            float b0 = bias[jg], b1 = bias[jg + 1];
#pragma unroll
            for (int h2 = 0; h2 < 2; h2++) {
                int row = row0 + h2 * 8;
                float v0 = c[mt][j][h2 * 2 + 0] + b0;
                float v1 = c[mt][j][h2 * 2 + 1] + b1;
                size_t idx = (size_t)row * UU + col;
                if (MODE == 0) {
                    float s0 = 1.f / (1.f + expf(-v0));
                    float s1 = 1.f / (1.f + expf(-v1));
                    if (jb == 0) {
                        float2 hh = *(const float2*)(hvec + idx);
                        __half2 o = __floats2half2_rn(s0 * hh.x, s1 * hh.y);
                        *(__half2*)(g_rh + idx) = o;
                    } else {
                        float2 o; o.x = s0; o.y = s1;
                        *(float2*)(g_u + idx) = o;
                    }
                } else {
                    float t0 = tanhf(v0), t1 = tanhf(v1);
                    float2 uu = *(const float2*)(g_u + idx);
                    float2 hh = *(const float2*)(hvec + idx);
                    float2 o;
                    o.x = uu.x * hh.x + (1.f - uu.x) * t0;
                    o.y = uu.y * hh.y + (1.f - uu.y) * t1;
                    *(float2*)(newh + idx) = o;
                    part[mt][h2] = fmaf(o.x, pw[col], part[mt][h2]);
                    part[mt][h2] = fmaf(o.y, pw[col + 1], part[mt][h2]);
                }
            }
        }
    }

    if (MODE == 1) {
        __syncthreads();               // SM reads done; safe to alias srow
        if (tid < 128) srow[tid] = 0.f;
        __syncthreads();
#pragma unroll
        for (int mt = 0; mt < 2; mt++)
#pragma unroll
            for (int h2 = 0; h2 < 2; h2++) {
                int lr = wm * 32 + mt * 16 + h2 * 8 + (lane >> 2);
                atomicAdd(&srow[lr], part[mt][h2]);
            }
        __syncthreads();
        if (tid < 128) out[mbase + tid] = srow[tid] + pb[0];
    }
}

// ---------------- launch ------------------------------------------------------
extern "C" void kernel_launch(void* const* d_in, const int* in_sizes, int n_in,
                              void* d_out, int out_size) {
    const float* inp = (const float*)d_in[0];
    const float* h   = (const float*)d_in[1];
    const float* S   = (const float*)d_in[2];
    const float* gw  = (const float*)d_in[3];
    const float* gb  = (const float*)d_in[4];
    const float* cw  = (const float*)d_in[5];
    const float* cb  = (const float*)d_in[6];
    const float* pw  = (const float*)d_in[7];
    const float* pb  = (const float*)d_in[8];
    float* out  = (float*)d_out;
    float* newh = out + MROWS;

    cudaFuncSetAttribute(gemm_kernel<0>, cudaFuncAttributeMaxDynamicSharedMemorySize, GSM_BYTES);
    cudaFuncSetAttribute(gemm_kernel<1>, cudaFuncAttributeMaxDynamicSharedMemorySize, GSM_BYTES);

    setup_all<<<SETUP_TOTAL, 256>>>(h, S, gw, cw);

    // gate path
    spmm_pass1<0><<<dim3(NN, BB / 4), 128>>>(inp);
    spmm_pass2<0><<<dim3(NN, BB / 4), 128>>>(inp);
    gemm_kernel<0><<<dim3(MROWS / 128, 2), 256, GSM_BYTES>>>(gb, h, nullptr, nullptr, nullptr, nullptr);

    // cand path (projection fused)
    spmm_pass1<1><<<dim3(NN, BB / 4), 128>>>(inp);
    spmm_pass2<1><<<dim3(NN, BB / 4), 128>>>(inp);
    gemm_kernel<1><<<dim3(MROWS / 128, 1), 256, GSM_BYTES>>>(cb, h, newh, pw, pb, out);
}